// round 6
// baseline (speedup 1.0000x reference)
#include <cuda_runtime.h>

#define Bq 32
#define Tq 512
#define Dq 128
#define Nq 1024
#define NOISE_C 0.001f
#define GRID_G 128
#define NCOL 8
#define NTHR 512
#define NW 16          // warps per CTA
#define KSL 64         // K-slice per warp
#define ITS 16         // KSL/4 float4 iterations

// States double buffer, k-blocked transposed: g_S4[phase][k/4][b] = float4 of S[b][4k..4k+3]
__device__ float4 g_S4[2][Nq / 4][Bq];
// Per-CTA monotonic flags (contention-free barrier). Reset by init_kernel each
// launch (stream-ordered before recur_kernel) -> deterministic & replay-safe.
__device__ unsigned g_flags[GRID_G];

// out[:,0,:] = step0 ; pack states0 into g_S4[0] ; reset barrier flags
__global__ void init_kernel(const float* __restrict__ states0,
                            const float* __restrict__ step0,
                            float* __restrict__ out) {
    int i = blockIdx.x * blockDim.x + threadIdx.x;  // 0 .. 32767
    int b = i >> 10;
    int n = i & 1023;
    out[(size_t)b * Tq * Nq + n] = step0[i];
    ((float*)&g_S4[0][n >> 2][b])[n & 3] = states0[i];
    if (i < GRID_G) g_flags[i] = 0u;
}

// xin GEMM: out[b,t,n] = scale * sum_d x[b,t,d] * w_input[d,n]   for t in [1,512)
__global__ __launch_bounds__(256) void xin_gemm(const float* __restrict__ x,
                                                const float* __restrict__ w_in,
                                                const float* __restrict__ scale_p,
                                                float* __restrict__ out) {
    __shared__ float xs[128][33];
    __shared__ float ws[32][132];
    __shared__ int rowoff[128];

    const int tid = threadIdx.x;
    const int tx = tid & 15;
    const int ty = tid >> 4;
    const int bn = blockIdx.x;   // 0..7
    const int bm = blockIdx.y;   // 0..127
    const float sc = *scale_p;

    if (tid < 128) {
        int m = bm * 128 + tid;
        if (m < Bq * (Tq - 1)) {
            int b = m / (Tq - 1);
            int t = m - b * (Tq - 1) + 1;
            rowoff[tid] = (b * Tq + t) * Dq;
        } else {
            rowoff[tid] = -1;
        }
    }

    float acc[8][8];
#pragma unroll
    for (int i = 0; i < 8; ++i)
#pragma unroll
        for (int j = 0; j < 8; ++j) acc[i][j] = 0.f;

    __syncthreads();

    for (int kc = 0; kc < 4; ++kc) {
#pragma unroll
        for (int l = 0; l < 16; ++l) {
            int idx = tid + l * 256;
            int r = idx >> 5, k = idx & 31;
            int ro = rowoff[r];
            xs[r][k] = (ro >= 0) ? x[(size_t)ro + kc * 32 + k] : 0.f;
        }
#pragma unroll
        for (int l = 0; l < 16; ++l) {
            int idx = tid + l * 256;
            int kk = idx >> 7, c = idx & 127;
            ws[kk][c] = w_in[(size_t)(kc * 32 + kk) * Nq + bn * 128 + c];
        }
        __syncthreads();

#pragma unroll
        for (int k = 0; k < 32; ++k) {
            float xr[8], wr[8];
#pragma unroll
            for (int i = 0; i < 8; ++i) xr[i] = xs[ty * 8 + i][k];
#pragma unroll
            for (int j = 0; j < 8; ++j) wr[j] = ws[k][tx * 8 + j];
#pragma unroll
            for (int i = 0; i < 8; ++i)
#pragma unroll
                for (int j = 0; j < 8; ++j) acc[i][j] += xr[i] * wr[j];
        }
        __syncthreads();
    }

#pragma unroll
    for (int i = 0; i < 8; ++i) {
        int ro = rowoff[ty * 8 + i];
        if (ro < 0) continue;
        float* op = out + (size_t)(ro >> 7) * Nq + bn * 128 + tx * 8;
#pragma unroll
        for (int j = 0; j < 8; ++j) op[j] = acc[i][j] * sc;
    }
}

// Persistent recurrence (R3 structure). 128 CTAs x 512 threads. CTA owns 8 columns
// of W_res in SMEM. Warp w reduces K-slice [64w, 64w+64), lane = batch.
// fp32x2 packed FMA; depth-8 pipelined L2-only state loads.
// Barrier: per-CTA release-flag (no per-address atomic contention) + one warp
// acquire-polling 4 flag lines -> detection ~1 L2 RTT.
__global__ __launch_bounds__(NTHR, 1) void recur_kernel(const float* __restrict__ w_res,
                                                        const float* __restrict__ noise,
                                                        float* __restrict__ out) {
    __shared__ __align__(16) float Wsm[Nq][NCOL];   // 32 KB
    __shared__ float red[NW][Bq][9];                // 18 KB, conflict-free writes

    const int tid = threadIdx.x;
    const int cta = blockIdx.x;
    const int col0 = cta * NCOL;

    for (int i = tid; i < Nq * NCOL; i += NTHR) {
        int k = i >> 3, c = i & 7;
        Wsm[k][c] = w_res[(size_t)k * Nq + col0 + c];
    }
    __syncthreads();

    const int warp = tid >> 5;
    const int lane = tid & 31;  // = batch b for the K-reduction

    // epilogue mapping (first 256 threads): thread -> (eb, ec)
    const bool epi = (tid < Bq * NCOL);
    const int eb = (tid >> 3) & 31;
    const int ec = tid & 7;
    const int en = col0 + ec;
    const float nz = epi ? NOISE_C * noise[eb * Nq + en] : 0.f;
    float* outp = out + (size_t)eb * Tq * Nq + en;
    float* sW0 = &((float*)&g_S4[0][en >> 2][eb])[en & 3];
    float* sW1 = &((float*)&g_S4[1][en >> 2][eb])[en & 3];

    const ulonglong2* Wp0 = (const ulonglong2*)&Wsm[warp * KSL][0];

    for (int t = 1; t < Tq; ++t) {
        const float4* Sp = ((const float4*)g_S4[(t - 1) & 1]) + warp * (ITS * Bq) + lane;

        float xin = epi ? outp[(size_t)t * Nq] : 0.f;  // barrier-independent; issue early

        // fill depth-8 pipeline of L2-only state loads
        float4 buf[8];
#pragma unroll
        for (int j = 0; j < 8; ++j) buf[j] = __ldcg(Sp + j * Bq);

        unsigned long long a0 = 0, a1 = 0, a2 = 0, a3 = 0;
        const ulonglong2* wp = Wp0;

#pragma unroll
        for (int it = 0; it < ITS; ++it) {
            float4 s = buf[it & 7];
            if (it < ITS - 8) buf[it & 7] = __ldcg(Sp + (it + 8) * Bq);
#pragma unroll
            for (int kk = 0; kk < 4; ++kk) {
                unsigned sb = __float_as_uint(kk == 0 ? s.x : kk == 1 ? s.y
                                                         : kk == 2 ? s.z : s.w);
                unsigned long long svv;
                asm("mov.b64 %0, {%1, %1};" : "=l"(svv) : "r"(sb));
                ulonglong2 u0 = wp[0];
                ulonglong2 u1 = wp[1];
                wp += 2;
                asm("fma.rn.f32x2 %0, %1, %2, %0;" : "+l"(a0) : "l"(svv), "l"(u0.x));
                asm("fma.rn.f32x2 %0, %1, %2, %0;" : "+l"(a1) : "l"(svv), "l"(u0.y));
                asm("fma.rn.f32x2 %0, %1, %2, %0;" : "+l"(a2) : "l"(svv), "l"(u1.x));
                asm("fma.rn.f32x2 %0, %1, %2, %0;" : "+l"(a3) : "l"(svv), "l"(u1.y));
            }
        }

        red[warp][lane][0] = __uint_as_float((unsigned)a0);
        red[warp][lane][1] = __uint_as_float((unsigned)(a0 >> 32));
        red[warp][lane][2] = __uint_as_float((unsigned)a1);
        red[warp][lane][3] = __uint_as_float((unsigned)(a1 >> 32));
        red[warp][lane][4] = __uint_as_float((unsigned)a2);
        red[warp][lane][5] = __uint_as_float((unsigned)(a2 >> 32));
        red[warp][lane][6] = __uint_as_float((unsigned)a3);
        red[warp][lane][7] = __uint_as_float((unsigned)(a3 >> 32));
        __syncthreads();

        if (epi) {
            float sum = 0.f;
#pragma unroll
            for (int w = 0; w < NW; ++w) sum += red[w][eb][ec];

            float post = tanhf(sum + xin) + nz;
            outp[(size_t)t * Nq] = post;        // only our own sector — safe
            *((t & 1) ? sW1 : sW0) = post;      // next-step state (read via __ldcg)
        }

        // ---- grid barrier: per-CTA release flag + warp-parallel acquire poll ----
        __syncthreads();  // all CTA state writes done; HB to thread 0
        if (warp == 0) {
            if (lane == 0) {
                asm volatile("st.release.gpu.u32 [%0], %1;"
                             :: "l"(&g_flags[cta]), "r"((unsigned)t) : "memory");
            }
            // each lane polls 4 flags (4 cache lines total, broadcast-dedup'd)
            bool ok;
            do {
                unsigned v0, v1, v2, v3;
                asm volatile("ld.acquire.gpu.u32 %0, [%1];"
                             : "=r"(v0) : "l"(&g_flags[lane]) : "memory");
                asm volatile("ld.acquire.gpu.u32 %0, [%1];"
                             : "=r"(v1) : "l"(&g_flags[lane + 32]) : "memory");
                asm volatile("ld.acquire.gpu.u32 %0, [%1];"
                             : "=r"(v2) : "l"(&g_flags[lane + 64]) : "memory");
                asm volatile("ld.acquire.gpu.u32 %0, [%1];"
                             : "=r"(v3) : "l"(&g_flags[lane + 96]) : "memory");
                ok = (v0 >= (unsigned)t) && (v1 >= (unsigned)t) &&
                     (v2 >= (unsigned)t) && (v3 >= (unsigned)t);
            } while (!__all_sync(0xffffffffu, ok));
        }
        __syncthreads();  // broadcast completion
    }
}

extern "C" void kernel_launch(void* const* d_in, const int* in_sizes, int n_in,
                              void* d_out, int out_size) {
    (void)in_sizes; (void)n_in; (void)out_size;
    const float* x       = (const float*)d_in[0];
    const float* w_input = (const float*)d_in[1];
    const float* w_res   = (const float*)d_in[2];
    const float* w_scale = (const float*)d_in[3];
    const float* states0 = (const float*)d_in[4];
    const float* step0   = (const float*)d_in[5];
    const float* rnoise  = (const float*)d_in[6];
    float* out = (float*)d_out;

    init_kernel<<<128, 256>>>(states0, step0, out);
    dim3 g(8, 128);
    xin_gemm<<<g, 256>>>(x, w_input, w_scale, out);
    recur_kernel<<<GRID_G, NTHR>>>(w_res, rnoise, out);
}

// round 7
// speedup vs baseline: 1.6450x; 1.6450x over previous
#include <cuda_runtime.h>

#define Bq 32
#define Tq 512
#define Dq 128
#define Nq 1024
#define NOISE_C 0.001f
#define GRID_G 128
#define NCOL 8
#define NTHR 512
#define NW 16          // warps per CTA
#define KSL 64         // K-slice per warp
#define ITS 16         // KSL/4 float4 iterations
#define NGRP 16        // barrier groups
#define GSZ 8          // CTAs per group

// States double buffer, k-blocked transposed: g_S4[phase][k/4][b] = float4 of S[b][4k..4k+3]
__device__ float4 g_S4[2][Nq / 4][Bq];
// Hierarchical barrier counters: one 128B line per group + one root line.
// Monotonic; reset by init_kernel each launch (stream-ordered) -> replay-safe.
__device__ unsigned g_grp[NGRP * 32];
__device__ unsigned g_root[32];

// out[:,0,:] = step0 ; pack states0 into g_S4[0] ; reset barrier counters
__global__ void init_kernel(const float* __restrict__ states0,
                            const float* __restrict__ step0,
                            float* __restrict__ out) {
    int i = blockIdx.x * blockDim.x + threadIdx.x;  // 0 .. 32767
    int b = i >> 10;
    int n = i & 1023;
    out[(size_t)b * Tq * Nq + n] = step0[i];
    ((float*)&g_S4[0][n >> 2][b])[n & 3] = states0[i];
    if (i < NGRP * 32) g_grp[i] = 0u;
    if (i < 32) g_root[i] = 0u;
}

// xin GEMM: out[b,t,n] = scale * sum_d x[b,t,d] * w_input[d,n]   for t in [1,512)
__global__ __launch_bounds__(256) void xin_gemm(const float* __restrict__ x,
                                                const float* __restrict__ w_in,
                                                const float* __restrict__ scale_p,
                                                float* __restrict__ out) {
    __shared__ float xs[128][33];
    __shared__ float ws[32][132];
    __shared__ int rowoff[128];

    const int tid = threadIdx.x;
    const int tx = tid & 15;
    const int ty = tid >> 4;
    const int bn = blockIdx.x;   // 0..7
    const int bm = blockIdx.y;   // 0..127
    const float sc = *scale_p;

    if (tid < 128) {
        int m = bm * 128 + tid;
        if (m < Bq * (Tq - 1)) {
            int b = m / (Tq - 1);
            int t = m - b * (Tq - 1) + 1;
            rowoff[tid] = (b * Tq + t) * Dq;
        } else {
            rowoff[tid] = -1;
        }
    }

    float acc[8][8];
#pragma unroll
    for (int i = 0; i < 8; ++i)
#pragma unroll
        for (int j = 0; j < 8; ++j) acc[i][j] = 0.f;

    __syncthreads();

    for (int kc = 0; kc < 4; ++kc) {
#pragma unroll
        for (int l = 0; l < 16; ++l) {
            int idx = tid + l * 256;
            int r = idx >> 5, k = idx & 31;
            int ro = rowoff[r];
            xs[r][k] = (ro >= 0) ? x[(size_t)ro + kc * 32 + k] : 0.f;
        }
#pragma unroll
        for (int l = 0; l < 16; ++l) {
            int idx = tid + l * 256;
            int kk = idx >> 7, c = idx & 127;
            ws[kk][c] = w_in[(size_t)(kc * 32 + kk) * Nq + bn * 128 + c];
        }
        __syncthreads();

#pragma unroll
        for (int k = 0; k < 32; ++k) {
            float xr[8], wr[8];
#pragma unroll
            for (int i = 0; i < 8; ++i) xr[i] = xs[ty * 8 + i][k];
#pragma unroll
            for (int j = 0; j < 8; ++j) wr[j] = ws[k][tx * 8 + j];
#pragma unroll
            for (int i = 0; i < 8; ++i)
#pragma unroll
                for (int j = 0; j < 8; ++j) acc[i][j] += xr[i] * wr[j];
        }
        __syncthreads();
    }

#pragma unroll
    for (int i = 0; i < 8; ++i) {
        int ro = rowoff[ty * 8 + i];
        if (ro < 0) continue;
        float* op = out + (size_t)(ro >> 7) * Nq + bn * 128 + tx * 8;
#pragma unroll
        for (int j = 0; j < 8; ++j) op[j] = acc[i][j] * sc;
    }
}

// Persistent recurrence (R4-best structure). 128 CTAs x 512 threads. CTA owns
// 8 columns of W_res in SMEM. Warp w reduces K-slice [64w, 64w+64), lane = batch.
// fp32x2 packed FMA; depth-8 pipelined L2-only state loads.
// Barrier: 2-level counters. 8 REDG arrivals per group line (parallel across 16
// groups), leader acquire-polls its group (sole reader), releases to root (16
// arrivals); everyone acquire-polls root with backoff.
__global__ __launch_bounds__(NTHR, 1) void recur_kernel(const float* __restrict__ w_res,
                                                        const float* __restrict__ noise,
                                                        float* __restrict__ out) {
    __shared__ __align__(16) float Wsm[Nq][NCOL];   // 32 KB
    __shared__ float red[NW][Bq][9];                // 18 KB, conflict-free

    const int tid = threadIdx.x;
    const int cta = blockIdx.x;
    const int col0 = cta * NCOL;
    const int grp = cta >> 3;                  // 0..15
    const bool leader = ((cta & 7) == 0);
    unsigned* grp_cnt = &g_grp[grp * 32];
    unsigned* root_cnt = &g_root[0];

    for (int i = tid; i < Nq * NCOL; i += NTHR) {
        int k = i >> 3, c = i & 7;
        Wsm[k][c] = w_res[(size_t)k * Nq + col0 + c];
    }
    __syncthreads();

    const int warp = tid >> 5;
    const int lane = tid & 31;  // = batch b for the K-reduction

    // epilogue mapping (first 256 threads): thread -> (eb, ec)
    const bool epi = (tid < Bq * NCOL);
    const int eb = (tid >> 3) & 31;
    const int ec = tid & 7;
    const int en = col0 + ec;
    const float nz = epi ? NOISE_C * noise[eb * Nq + en] : 0.f;
    float* outp = out + (size_t)eb * Tq * Nq + en;
    float* sW0 = &((float*)&g_S4[0][en >> 2][eb])[en & 3];
    float* sW1 = &((float*)&g_S4[1][en >> 2][eb])[en & 3];

    const ulonglong2* Wp0 = (const ulonglong2*)&Wsm[warp * KSL][0];

    for (int t = 1; t < Tq; ++t) {
        const float4* Sp = ((const float4*)g_S4[(t - 1) & 1]) + warp * (ITS * Bq) + lane;

        float xin = epi ? outp[(size_t)t * Nq] : 0.f;  // barrier-independent; issue early

        // fill depth-8 pipeline of L2-only state loads
        float4 buf[8];
#pragma unroll
        for (int j = 0; j < 8; ++j) buf[j] = __ldcg(Sp + j * Bq);

        unsigned long long a0 = 0, a1 = 0, a2 = 0, a3 = 0;
        const ulonglong2* wp = Wp0;

#pragma unroll
        for (int it = 0; it < ITS; ++it) {
            float4 s = buf[it & 7];
            if (it < ITS - 8) buf[it & 7] = __ldcg(Sp + (it + 8) * Bq);
#pragma unroll
            for (int kk = 0; kk < 4; ++kk) {
                unsigned sb = __float_as_uint(kk == 0 ? s.x : kk == 1 ? s.y
                                                         : kk == 2 ? s.z : s.w);
                unsigned long long svv;
                asm("mov.b64 %0, {%1, %1};" : "=l"(svv) : "r"(sb));
                ulonglong2 u0 = wp[0];
                ulonglong2 u1 = wp[1];
                wp += 2;
                asm("fma.rn.f32x2 %0, %1, %2, %0;" : "+l"(a0) : "l"(svv), "l"(u0.x));
                asm("fma.rn.f32x2 %0, %1, %2, %0;" : "+l"(a1) : "l"(svv), "l"(u0.y));
                asm("fma.rn.f32x2 %0, %1, %2, %0;" : "+l"(a2) : "l"(svv), "l"(u1.x));
                asm("fma.rn.f32x2 %0, %1, %2, %0;" : "+l"(a3) : "l"(svv), "l"(u1.y));
            }
        }

        red[warp][lane][0] = __uint_as_float((unsigned)a0);
        red[warp][lane][1] = __uint_as_float((unsigned)(a0 >> 32));
        red[warp][lane][2] = __uint_as_float((unsigned)a1);
        red[warp][lane][3] = __uint_as_float((unsigned)(a1 >> 32));
        red[warp][lane][4] = __uint_as_float((unsigned)a2);
        red[warp][lane][5] = __uint_as_float((unsigned)(a2 >> 32));
        red[warp][lane][6] = __uint_as_float((unsigned)a3);
        red[warp][lane][7] = __uint_as_float((unsigned)(a3 >> 32));
        __syncthreads();

        if (epi) {
            float sum = 0.f;
#pragma unroll
            for (int w = 0; w < NW; ++w) sum += red[w][eb][ec];

            float post = tanhf(sum + xin) + nz;
            outp[(size_t)t * Nq] = post;        // only our own sector — safe
            *((t & 1) ? sW1 : sW0) = post;      // next-step state (read via __ldcg)
        }

        // ---- hierarchical grid barrier ----
        __syncthreads();  // all CTA state writes done; HB to thread 0
        if (tid == 0) {
            // level 1: arrive at group counter (release publishes our state writes)
            asm volatile("red.release.gpu.add.u32 [%0], %1;"
                         :: "l"(grp_cnt), "r"(1u) : "memory");
            if (leader) {
                // sole reader of this line: tight acquire poll
                const unsigned gtarget = (unsigned)GSZ * (unsigned)t;
                unsigned v;
                do {
                    asm volatile("ld.acquire.gpu.u32 %0, [%1];"
                                 : "=r"(v) : "l"(grp_cnt) : "memory");
                } while (v < gtarget);
                // level 2: arrive at root (release after acquiring group -> HB chain)
                asm volatile("red.release.gpu.add.u32 [%0], %1;"
                             :: "l"(root_cnt), "r"(1u) : "memory");
            }
            // everyone: poll root with backoff
            const unsigned rtarget = (unsigned)NGRP * (unsigned)t;
            unsigned v;
            do {
                asm volatile("ld.acquire.gpu.u32 %0, [%1];"
                             : "=r"(v) : "l"(root_cnt) : "memory");
                if (v < rtarget) __nanosleep(16);
            } while (v < rtarget);
        }
        __syncthreads();  // broadcast completion
    }
}

extern "C" void kernel_launch(void* const* d_in, const int* in_sizes, int n_in,
                              void* d_out, int out_size) {
    (void)in_sizes; (void)n_in; (void)out_size;
    const float* x       = (const float*)d_in[0];
    const float* w_input = (const float*)d_in[1];
    const float* w_res   = (const float*)d_in[2];
    const float* w_scale = (const float*)d_in[3];
    const float* states0 = (const float*)d_in[4];
    const float* step0   = (const float*)d_in[5];
    const float* rnoise  = (const float*)d_in[6];
    float* out = (float*)d_out;

    init_kernel<<<128, 256>>>(states0, step0, out);
    dim3 g(8, 128);
    xin_gemm<<<g, 256>>>(x, w_input, w_scale, out);
    recur_kernel<<<GRID_G, NTHR>>>(w_res, rnoise, out);
}

// round 8
// speedup vs baseline: 1.9317x; 1.1743x over previous
#include <cuda_runtime.h>

#define Bq 32
#define Tq 512
#define Dq 128
#define Nq 1024
#define NOISE_C 0.001f
#define GRID_G 128
#define NCOL 8
#define NTHR 512
#define NW 16          // warps per CTA
#define PH_K 32        // k per warp per phase
#define PH_IT 8        // float4 iterations per phase

// States double buffer, k-blocked transposed: g_S4[phase][k/4][b] = float4 of S[b][4k..4k+3]
__device__ float4 g_S4[2][Nq / 4][Bq];
// Two gang counters (separate 128B lines). Gang A = CTAs 0..63 (cols/k 0..511),
// gang B = CTAs 64..127. Monotonic; reset by init_kernel each launch -> replay-safe.
__device__ unsigned g_cnt2[64];

// out[:,0,:] = step0 ; pack states0 into g_S4[0] ; reset counters
__global__ void init_kernel(const float* __restrict__ states0,
                            const float* __restrict__ step0,
                            float* __restrict__ out) {
    int i = blockIdx.x * blockDim.x + threadIdx.x;  // 0 .. 32767
    int b = i >> 10;
    int n = i & 1023;
    out[(size_t)b * Tq * Nq + n] = step0[i];
    ((float*)&g_S4[0][n >> 2][b])[n & 3] = states0[i];
    if (i < 64) g_cnt2[i] = 0u;
}

// xin GEMM: out[b,t,n] = scale * sum_d x[b,t,d] * w_input[d,n]   for t in [1,512)
__global__ __launch_bounds__(256) void xin_gemm(const float* __restrict__ x,
                                                const float* __restrict__ w_in,
                                                const float* __restrict__ scale_p,
                                                float* __restrict__ out) {
    __shared__ float xs[128][33];
    __shared__ float ws[32][132];
    __shared__ int rowoff[128];

    const int tid = threadIdx.x;
    const int tx = tid & 15;
    const int ty = tid >> 4;
    const int bn = blockIdx.x;   // 0..7
    const int bm = blockIdx.y;   // 0..127
    const float sc = *scale_p;

    if (tid < 128) {
        int m = bm * 128 + tid;
        if (m < Bq * (Tq - 1)) {
            int b = m / (Tq - 1);
            int t = m - b * (Tq - 1) + 1;
            rowoff[tid] = (b * Tq + t) * Dq;
        } else {
            rowoff[tid] = -1;
        }
    }

    float acc[8][8];
#pragma unroll
    for (int i = 0; i < 8; ++i)
#pragma unroll
        for (int j = 0; j < 8; ++j) acc[i][j] = 0.f;

    __syncthreads();

    for (int kc = 0; kc < 4; ++kc) {
#pragma unroll
        for (int l = 0; l < 16; ++l) {
            int idx = tid + l * 256;
            int r = idx >> 5, k = idx & 31;
            int ro = rowoff[r];
            xs[r][k] = (ro >= 0) ? x[(size_t)ro + kc * 32 + k] : 0.f;
        }
#pragma unroll
        for (int l = 0; l < 16; ++l) {
            int idx = tid + l * 256;
            int kk = idx >> 7, c = idx & 127;
            ws[kk][c] = w_in[(size_t)(kc * 32 + kk) * Nq + bn * 128 + c];
        }
        __syncthreads();

#pragma unroll
        for (int k = 0; k < 32; ++k) {
            float xr[8], wr[8];
#pragma unroll
            for (int i = 0; i < 8; ++i) xr[i] = xs[ty * 8 + i][k];
#pragma unroll
            for (int j = 0; j < 8; ++j) wr[j] = ws[k][tx * 8 + j];
#pragma unroll
            for (int i = 0; i < 8; ++i)
#pragma unroll
                for (int j = 0; j < 8; ++j) acc[i][j] += xr[i] * wr[j];
        }
        __syncthreads();
    }

#pragma unroll
    for (int i = 0; i < 8; ++i) {
        int ro = rowoff[ty * 8 + i];
        if (ro < 0) continue;
        float* op = out + (size_t)(ro >> 7) * Nq + bn * 128 + tx * 8;
#pragma unroll
        for (int j = 0; j < 8; ++j) op[j] = acc[i][j] * sc;
    }
}

// one phase of the K-reduction: 8 prefetched float4 state rows x 8 W columns
__device__ __forceinline__ void phase_fma(const float4* Sp, const ulonglong2* wp,
                                          unsigned long long& a0, unsigned long long& a1,
                                          unsigned long long& a2, unsigned long long& a3) {
    float4 buf[PH_IT];
#pragma unroll
    for (int j = 0; j < PH_IT; ++j) buf[j] = __ldcg(Sp + j * Bq);
#pragma unroll
    for (int it = 0; it < PH_IT; ++it) {
        float4 s = buf[it];
#pragma unroll
        for (int kk = 0; kk < 4; ++kk) {
            unsigned sb = __float_as_uint(kk == 0 ? s.x : kk == 1 ? s.y
                                                     : kk == 2 ? s.z : s.w);
            unsigned long long svv;
            asm("mov.b64 %0, {%1, %1};" : "=l"(svv) : "r"(sb));
            ulonglong2 u0 = wp[0];
            ulonglong2 u1 = wp[1];
            wp += 2;
            asm("fma.rn.f32x2 %0, %1, %2, %0;" : "+l"(a0) : "l"(svv), "l"(u0.x));
            asm("fma.rn.f32x2 %0, %1, %2, %0;" : "+l"(a1) : "l"(svv), "l"(u0.y));
            asm("fma.rn.f32x2 %0, %1, %2, %0;" : "+l"(a2) : "l"(svv), "l"(u1.x));
            asm("fma.rn.f32x2 %0, %1, %2, %0;" : "+l"(a3) : "l"(svv), "l"(u1.y));
        }
    }
}

// Persistent recurrence. 128 CTAs x 512 threads. CTA owns 8 columns of W_res in
// SMEM. Split-K double barrier: wait gang-A -> compute k[0,512) -> wait gang-B
// (latency hidden behind phase 1) -> compute k[512,1024). Warp w covers 32 k
// per phase; lane = batch. fp32x2 packed FMA throughout.
__global__ __launch_bounds__(NTHR, 1) void recur_kernel(const float* __restrict__ w_res,
                                                        const float* __restrict__ noise,
                                                        float* __restrict__ out) {
    __shared__ __align__(16) float Wsm[Nq][NCOL];   // 32 KB
    __shared__ float red[NW][Bq][9];                // 18 KB, conflict-free

    const int tid = threadIdx.x;
    const int cta = blockIdx.x;
    const int col0 = cta * NCOL;
    unsigned* mycnt = &g_cnt2[(cta < 64) ? 0 : 32];
    unsigned* cntA = &g_cnt2[0];
    unsigned* cntB = &g_cnt2[32];

    for (int i = tid; i < Nq * NCOL; i += NTHR) {
        int k = i >> 3, c = i & 7;
        Wsm[k][c] = w_res[(size_t)k * Nq + col0 + c];
    }
    __syncthreads();

    const int warp = tid >> 5;
    const int lane = tid & 31;  // = batch b for the K-reduction

    // epilogue mapping (first 256 threads): thread -> (eb, ec)
    const bool epi = (tid < Bq * NCOL);
    const int eb = (tid >> 3) & 31;
    const int ec = tid & 7;
    const int en = col0 + ec;
    const float nz = epi ? NOISE_C * noise[eb * Nq + en] : 0.f;
    float* outp = out + (size_t)eb * Tq * Nq + en;
    float* sW0 = &((float*)&g_S4[0][en >> 2][eb])[en & 3];
    float* sW1 = &((float*)&g_S4[1][en >> 2][eb])[en & 3];

    const ulonglong2* WpA = (const ulonglong2*)&Wsm[warp * PH_K][0];
    const ulonglong2* WpB = (const ulonglong2*)&Wsm[512 + warp * PH_K][0];

    for (int t = 1; t < Tq; ++t) {
        const float4* Sbase = (const float4*)g_S4[(t - 1) & 1];
        const unsigned tgt = 64u * (unsigned)(t - 1);  // arrivals of previous step

        float xin = epi ? outp[(size_t)t * Nq] : 0.f;  // own data; barrier-independent

        // ---- wait gang A (k half [0,512) ready) ----
        if (tid == 0) {
            unsigned v;
            do {
                asm volatile("ld.acquire.gpu.u32 %0, [%1];"
                             : "=r"(v) : "l"(cntA) : "memory");
            } while (v < tgt);
        }
        __syncthreads();

        unsigned long long a0 = 0, a1 = 0, a2 = 0, a3 = 0;
        // phase 1: warp w covers k [32w, 32w+32) -> float4 rows [8w, 8w+8)
        phase_fma(Sbase + (warp * PH_IT) * Bq + lane, WpA, a0, a1, a2, a3);

        // ---- wait gang B (latency hidden behind phase 1) ----
        if (tid == 0) {
            unsigned v;
            do {
                asm volatile("ld.acquire.gpu.u32 %0, [%1];"
                             : "=r"(v) : "l"(cntB) : "memory");
            } while (v < tgt);
        }
        __syncthreads();

        // phase 2: k [512 + 32w, 512 + 32w + 32)
        phase_fma(Sbase + (128 + warp * PH_IT) * Bq + lane, WpB, a0, a1, a2, a3);

        red[warp][lane][0] = __uint_as_float((unsigned)a0);
        red[warp][lane][1] = __uint_as_float((unsigned)(a0 >> 32));
        red[warp][lane][2] = __uint_as_float((unsigned)a1);
        red[warp][lane][3] = __uint_as_float((unsigned)(a1 >> 32));
        red[warp][lane][4] = __uint_as_float((unsigned)a2);
        red[warp][lane][5] = __uint_as_float((unsigned)(a2 >> 32));
        red[warp][lane][6] = __uint_as_float((unsigned)a3);
        red[warp][lane][7] = __uint_as_float((unsigned)(a3 >> 32));
        __syncthreads();

        if (epi) {
            float sum = 0.f;
#pragma unroll
            for (int w = 0; w < NW; ++w) sum += red[w][eb][ec];

            float post = tanhf(sum + xin) + nz;
            outp[(size_t)t * Nq] = post;        // only our own sector — safe
            *((t & 1) ? sW1 : sW0) = post;      // next-step state (read via __ldcg)
        }

        // ---- arrive at own gang counter (release publishes state writes) ----
        __syncthreads();  // all CTA state writes done; HB to thread 0
        if (tid == 0) {
            asm volatile("red.release.gpu.add.u32 [%0], %1;"
                         :: "l"(mycnt), "r"(1u) : "memory");
        }
    }
}

extern "C" void kernel_launch(void* const* d_in, const int* in_sizes, int n_in,
                              void* d_out, int out_size) {
    (void)in_sizes; (void)n_in; (void)out_size;
    const float* x       = (const float*)d_in[0];
    const float* w_input = (const float*)d_in[1];
    const float* w_res   = (const float*)d_in[2];
    const float* w_scale = (const float*)d_in[3];
    const float* states0 = (const float*)d_in[4];
    const float* step0   = (const float*)d_in[5];
    const float* rnoise  = (const float*)d_in[6];
    float* out = (float*)d_out;

    init_kernel<<<128, 256>>>(states0, step0, out);
    dim3 g(8, 128);
    xin_gemm<<<g, 256>>>(x, w_input, w_scale, out);
    recur_kernel<<<GRID_G, NTHR>>>(w_res, rnoise, out);
}

// round 9
// speedup vs baseline: 2.2200x; 1.1493x over previous
#include <cuda_runtime.h>

#define Bq 32
#define Tq 512
#define Dq 128
#define Nq 1024
#define NOISE_C 0.001f
#define GRID_G 128
#define NCOL 8
#define NTHR 512
#define NW 16          // warps per CTA
#define KSL 64         // k per warp (= one chunk)
#define ITS 16         // float4 iterations per warp
#define NGRP 16        // producer groups / chunks
#define GSZ 8          // CTAs per group

// States double buffer, k-blocked transposed: g_S4[phase][k/4][b] = float4 of S[b][4k..4k+3]
__device__ float4 g_S4[2][Nq / 4][Bq];
// 16 group counters, one 128B line each. Group g = CTAs [8g,8g+8) = cols/k chunk
// [64g, 64g+64). Monotonic; reset by init_kernel each launch -> replay-safe.
__device__ unsigned g_gcnt[NGRP * 32];

// out[:,0,:] = step0 ; pack states0 into g_S4[0] ; reset counters
__global__ void init_kernel(const float* __restrict__ states0,
                            const float* __restrict__ step0,
                            float* __restrict__ out) {
    int i = blockIdx.x * blockDim.x + threadIdx.x;  // 0 .. 32767
    int b = i >> 10;
    int n = i & 1023;
    out[(size_t)b * Tq * Nq + n] = step0[i];
    ((float*)&g_S4[0][n >> 2][b])[n & 3] = states0[i];
    if (i < NGRP * 32) g_gcnt[i] = 0u;
}

// xin GEMM: out[b,t,n] = scale * sum_d x[b,t,d] * w_input[d,n]   for t in [1,512)
__global__ __launch_bounds__(256) void xin_gemm(const float* __restrict__ x,
                                                const float* __restrict__ w_in,
                                                const float* __restrict__ scale_p,
                                                float* __restrict__ out) {
    __shared__ float xs[128][33];
    __shared__ float ws[32][132];
    __shared__ int rowoff[128];

    const int tid = threadIdx.x;
    const int tx = tid & 15;
    const int ty = tid >> 4;
    const int bn = blockIdx.x;   // 0..7
    const int bm = blockIdx.y;   // 0..127
    const float sc = *scale_p;

    if (tid < 128) {
        int m = bm * 128 + tid;
        if (m < Bq * (Tq - 1)) {
            int b = m / (Tq - 1);
            int t = m - b * (Tq - 1) + 1;
            rowoff[tid] = (b * Tq + t) * Dq;
        } else {
            rowoff[tid] = -1;
        }
    }

    float acc[8][8];
#pragma unroll
    for (int i = 0; i < 8; ++i)
#pragma unroll
        for (int j = 0; j < 8; ++j) acc[i][j] = 0.f;

    __syncthreads();

    for (int kc = 0; kc < 4; ++kc) {
#pragma unroll
        for (int l = 0; l < 16; ++l) {
            int idx = tid + l * 256;
            int r = idx >> 5, k = idx & 31;
            int ro = rowoff[r];
            xs[r][k] = (ro >= 0) ? x[(size_t)ro + kc * 32 + k] : 0.f;
        }
#pragma unroll
        for (int l = 0; l < 16; ++l) {
            int idx = tid + l * 256;
            int kk = idx >> 7, c = idx & 127;
            ws[kk][c] = w_in[(size_t)(kc * 32 + kk) * Nq + bn * 128 + c];
        }
        __syncthreads();

#pragma unroll
        for (int k = 0; k < 32; ++k) {
            float xr[8], wr[8];
#pragma unroll
            for (int i = 0; i < 8; ++i) xr[i] = xs[ty * 8 + i][k];
#pragma unroll
            for (int j = 0; j < 8; ++j) wr[j] = ws[k][tx * 8 + j];
#pragma unroll
            for (int i = 0; i < 8; ++i)
#pragma unroll
                for (int j = 0; j < 8; ++j) acc[i][j] += xr[i] * wr[j];
        }
        __syncthreads();
    }

#pragma unroll
    for (int i = 0; i < 8; ++i) {
        int ro = rowoff[ty * 8 + i];
        if (ro < 0) continue;
        float* op = out + (size_t)(ro >> 7) * Nq + bn * 128 + tx * 8;
#pragma unroll
        for (int j = 0; j < 8; ++j) op[j] = acc[i][j] * sc;
    }
}

// Persistent recurrence with per-warp dataflow gating. 128 CTAs x 512 threads.
// CTA owns 8 cols of W_res in SMEM. Warp w consumes k chunk [64w,64w+64), which
// is produced by group w (CTAs 8w..8w+7). Each warp gates ONLY on its chunk's
// counter -> arrival spread overlaps compute instead of serializing behind a
// full barrier. fp32x2 packed FMA; all-16 prefetched L2-only state loads.
__global__ __launch_bounds__(NTHR, 1) void recur_kernel(const float* __restrict__ w_res,
                                                        const float* __restrict__ noise,
                                                        float* __restrict__ out) {
    __shared__ __align__(16) float Wsm[Nq][NCOL];   // 32 KB
    __shared__ float red[NW][Bq][9];                // 18 KB, conflict-free

    const int tid = threadIdx.x;
    const int cta = blockIdx.x;
    const int col0 = cta * NCOL;
    unsigned* own_cnt = &g_gcnt[(cta >> 3) * 32];   // our group's counter

    for (int i = tid; i < Nq * NCOL; i += NTHR) {
        int k = i >> 3, c = i & 7;
        Wsm[k][c] = w_res[(size_t)k * Nq + col0 + c];
    }
    __syncthreads();

    const int warp = tid >> 5;
    const int lane = tid & 31;  // = batch b for the K-reduction
    unsigned* my_chunk_cnt = &g_gcnt[warp * 32];    // counter gating THIS warp's k chunk

    // epilogue mapping (first 256 threads): thread -> (eb, ec)
    const bool epi = (tid < Bq * NCOL);
    const int eb = (tid >> 3) & 31;
    const int ec = tid & 7;
    const int en = col0 + ec;
    const float nz = epi ? NOISE_C * noise[eb * Nq + en] : 0.f;
    float* outp = out + (size_t)eb * Tq * Nq + en;
    float* sW0 = &((float*)&g_S4[0][en >> 2][eb])[en & 3];
    float* sW1 = &((float*)&g_S4[1][en >> 2][eb])[en & 3];

    const ulonglong2* Wp0 = (const ulonglong2*)&Wsm[warp * KSL][0];

    for (int t = 1; t < Tq; ++t) {
        const float4* Sp = ((const float4*)g_S4[(t - 1) & 1]) + warp * (ITS * Bq) + lane;

        float xin = epi ? outp[(size_t)t * Nq] : 0.f;  // own data; gate-independent

        // ---- per-warp gate: wait for OUR chunk's producers (prev step) ----
        const unsigned tgt = (unsigned)GSZ * (unsigned)(t - 1);
        if (lane == 0) {
            unsigned v;
            do {
                asm volatile("ld.acquire.gpu.u32 %0, [%1];"
                             : "=r"(v) : "l"(my_chunk_cnt) : "memory");
                if (v < tgt) __nanosleep(8);
            } while (v < tgt);
        }
        __syncwarp();

        // prefetch entire chunk: 16 L2-only float4 loads, MLP=16
        float4 buf[ITS];
#pragma unroll
        for (int j = 0; j < ITS; ++j) buf[j] = __ldcg(Sp + j * Bq);

        unsigned long long a0 = 0, a1 = 0, a2 = 0, a3 = 0;
        const ulonglong2* wp = Wp0;

#pragma unroll
        for (int it = 0; it < ITS; ++it) {
            float4 s = buf[it];
#pragma unroll
            for (int kk = 0; kk < 4; ++kk) {
                unsigned sb = __float_as_uint(kk == 0 ? s.x : kk == 1 ? s.y
                                                         : kk == 2 ? s.z : s.w);
                unsigned long long svv;
                asm("mov.b64 %0, {%1, %1};" : "=l"(svv) : "r"(sb));
                ulonglong2 u0 = wp[0];
                ulonglong2 u1 = wp[1];
                wp += 2;
                asm("fma.rn.f32x2 %0, %1, %2, %0;" : "+l"(a0) : "l"(svv), "l"(u0.x));
                asm("fma.rn.f32x2 %0, %1, %2, %0;" : "+l"(a1) : "l"(svv), "l"(u0.y));
                asm("fma.rn.f32x2 %0, %1, %2, %0;" : "+l"(a2) : "l"(svv), "l"(u1.x));
                asm("fma.rn.f32x2 %0, %1, %2, %0;" : "+l"(a3) : "l"(svv), "l"(u1.y));
            }
        }

        red[warp][lane][0] = __uint_as_float((unsigned)a0);
        red[warp][lane][1] = __uint_as_float((unsigned)(a0 >> 32));
        red[warp][lane][2] = __uint_as_float((unsigned)a1);
        red[warp][lane][3] = __uint_as_float((unsigned)(a1 >> 32));
        red[warp][lane][4] = __uint_as_float((unsigned)a2);
        red[warp][lane][5] = __uint_as_float((unsigned)(a2 >> 32));
        red[warp][lane][6] = __uint_as_float((unsigned)a3);
        red[warp][lane][7] = __uint_as_float((unsigned)(a3 >> 32));
        __syncthreads();

        if (epi) {
            float sum = 0.f;
#pragma unroll
            for (int w = 0; w < NW; ++w) sum += red[w][eb][ec];

            float post = tanhf(sum + xin) + nz;
            outp[(size_t)t * Nq] = post;        // only our own sector — safe
            *((t & 1) ? sW1 : sW0) = post;      // next-step state (read via __ldcg)
        }

        // ---- arrive at own group counter (release publishes state writes) ----
        __syncthreads();  // all CTA state writes done; HB to thread 0
        if (tid == 0) {
            asm volatile("red.release.gpu.add.u32 [%0], %1;"
                         :: "l"(own_cnt), "r"(1u) : "memory");
        }
    }
}

extern "C" void kernel_launch(void* const* d_in, const int* in_sizes, int n_in,
                              void* d_out, int out_size) {
    (void)in_sizes; (void)n_in; (void)out_size;
    const float* x       = (const float*)d_in[0];
    const float* w_input = (const float*)d_in[1];
    const float* w_res   = (const float*)d_in[2];
    const float* w_scale = (const float*)d_in[3];
    const float* states0 = (const float*)d_in[4];
    const float* step0   = (const float*)d_in[5];
    const float* rnoise  = (const float*)d_in[6];
    float* out = (float*)d_out;

    // order: xin, init, recur (recur = launch index 5 -> ncu -s 5 captures it)
    dim3 g(8, 128);
    xin_gemm<<<g, 256>>>(x, w_input, w_scale, out);
    init_kernel<<<128, 256>>>(states0, step0, out);
    recur_kernel<<<GRID_G, NTHR>>>(w_res, rnoise, out);
}

// round 10
// speedup vs baseline: 2.2778x; 1.0260x over previous
#include <cuda_runtime.h>

#define Bq 32
#define Tq 512
#define Dq 128
#define Nq 1024
#define NOISE_C 0.001f
#define GRID_G 128
#define NCOL 8
#define NTHR 512
#define NW 16          // warps per CTA
#define KSL 64         // k per warp (= one chunk)
#define ITS 16         // float4 iterations per warp
#define NGRP 16        // producer groups / chunks
#define GSZ 8          // CTAs per group

// States double buffer, k-blocked transposed: g_S4[phase][k/4][b] = float4 of S[b][4k..4k+3]
__device__ float4 g_S4[2][Nq / 4][Bq];
// 16 group counters, one 128B line each. Group g = CTAs [8g,8g+8) = cols/k chunk
// [64g, 64g+64). Monotonic; reset by init_kernel each launch -> replay-safe.
__device__ unsigned g_gcnt[NGRP * 32];

// out[:,0,:] = step0 ; pack states0 into g_S4[0] ; reset counters
__global__ void init_kernel(const float* __restrict__ states0,
                            const float* __restrict__ step0,
                            float* __restrict__ out) {
    int i = blockIdx.x * blockDim.x + threadIdx.x;  // 0 .. 32767
    int b = i >> 10;
    int n = i & 1023;
    out[(size_t)b * Tq * Nq + n] = step0[i];
    ((float*)&g_S4[0][n >> 2][b])[n & 3] = states0[i];
    if (i < NGRP * 32) g_gcnt[i] = 0u;
}

// xin GEMM: out[b,t,n] = scale * sum_d x[b,t,d] * w_input[d,n]   for t in [1,512)
// 512 threads, thread tile 4 rows x 8 cols, packed f32x2 FMA accumulators.
// x broadcast from SMEM (address depends on ty only); W via 2x LDS.128 per k.
__global__ __launch_bounds__(512) void xin_gemm(const float* __restrict__ x,
                                                const float* __restrict__ w_in,
                                                const float* __restrict__ scale_p,
                                                float* __restrict__ out) {
    __shared__ float xs[128][33];
    __shared__ __align__(16) float ws[32][132];
    __shared__ int rowoff[128];

    const int tid = threadIdx.x;
    const int tx = tid & 15;     // col group: 8 cols each
    const int ty = tid >> 4;     // row group: 4 rows each (0..31)
    const int bn = blockIdx.x;   // 0..7
    const int bm = blockIdx.y;   // 0..127
    const float sc = *scale_p;

    if (tid < 128) {
        int m = bm * 128 + tid;
        if (m < Bq * (Tq - 1)) {
            int b = m / (Tq - 1);
            int t = m - b * (Tq - 1) + 1;
            rowoff[tid] = (b * Tq + t) * Dq;
        } else {
            rowoff[tid] = -1;
        }
    }

    unsigned long long acc[4][4];
#pragma unroll
    for (int i = 0; i < 4; ++i)
#pragma unroll
        for (int j = 0; j < 4; ++j) acc[i][j] = 0ull;

    __syncthreads();

    for (int kc = 0; kc < 4; ++kc) {
#pragma unroll
        for (int l = 0; l < 8; ++l) {            // 128x32 x-tile
            int idx = tid + l * 512;
            int r = idx >> 5, k = idx & 31;
            int ro = rowoff[r];
            xs[r][k] = (ro >= 0) ? x[(size_t)ro + kc * 32 + k] : 0.f;
        }
#pragma unroll
        for (int l = 0; l < 8; ++l) {            // 32x128 w-tile
            int idx = tid + l * 512;
            int kk = idx >> 7, c = idx & 127;
            ws[kk][c] = w_in[(size_t)(kc * 32 + kk) * Nq + bn * 128 + c];
        }
        __syncthreads();

#pragma unroll
        for (int k = 0; k < 32; ++k) {
            float xr[4];
#pragma unroll
            for (int i = 0; i < 4; ++i) xr[i] = xs[ty * 4 + i][k];  // warp-broadcast
            const ulonglong2* wsp = (const ulonglong2*)&ws[k][tx * 8];
            ulonglong2 w0 = wsp[0];
            ulonglong2 w1 = wsp[1];
#pragma unroll
            for (int i = 0; i < 4; ++i) {
                unsigned xb = __float_as_uint(xr[i]);
                unsigned long long xv;
                asm("mov.b64 %0, {%1, %1};" : "=l"(xv) : "r"(xb));
                asm("fma.rn.f32x2 %0, %1, %2, %0;" : "+l"(acc[i][0]) : "l"(xv), "l"(w0.x));
                asm("fma.rn.f32x2 %0, %1, %2, %0;" : "+l"(acc[i][1]) : "l"(xv), "l"(w0.y));
                asm("fma.rn.f32x2 %0, %1, %2, %0;" : "+l"(acc[i][2]) : "l"(xv), "l"(w1.x));
                asm("fma.rn.f32x2 %0, %1, %2, %0;" : "+l"(acc[i][3]) : "l"(xv), "l"(w1.y));
            }
        }
        __syncthreads();
    }

#pragma unroll
    for (int i = 0; i < 4; ++i) {
        int ro = rowoff[ty * 4 + i];
        if (ro < 0) continue;
        float4* op = (float4*)(out + (size_t)(ro >> 7) * Nq + bn * 128 + tx * 8);
        float4 v0, v1;
        v0.x = __uint_as_float((unsigned)acc[i][0]) * sc;
        v0.y = __uint_as_float((unsigned)(acc[i][0] >> 32)) * sc;
        v0.z = __uint_as_float((unsigned)acc[i][1]) * sc;
        v0.w = __uint_as_float((unsigned)(acc[i][1] >> 32)) * sc;
        v1.x = __uint_as_float((unsigned)acc[i][2]) * sc;
        v1.y = __uint_as_float((unsigned)(acc[i][2] >> 32)) * sc;
        v1.z = __uint_as_float((unsigned)acc[i][3]) * sc;
        v1.w = __uint_as_float((unsigned)(acc[i][3] >> 32)) * sc;
        op[0] = v0;
        op[1] = v1;
    }
}

// Persistent recurrence with per-warp dataflow gating (R8 winner, unchanged).
// 128 CTAs x 512 threads. CTA owns 8 cols of W_res in SMEM. Warp w consumes
// k chunk [64w,64w+64), produced by group w (CTAs 8w..8w+7). Each warp gates
// ONLY on its chunk's counter -> arrival spread overlaps compute.
__global__ __launch_bounds__(NTHR, 1) void recur_kernel(const float* __restrict__ w_res,
                                                        const float* __restrict__ noise,
                                                        float* __restrict__ out) {
    __shared__ __align__(16) float Wsm[Nq][NCOL];   // 32 KB
    __shared__ float red[NW][Bq][9];                // 18 KB, conflict-free

    const int tid = threadIdx.x;
    const int cta = blockIdx.x;
    const int col0 = cta * NCOL;
    unsigned* own_cnt = &g_gcnt[(cta >> 3) * 32];   // our group's counter

    for (int i = tid; i < Nq * NCOL; i += NTHR) {
        int k = i >> 3, c = i & 7;
        Wsm[k][c] = w_res[(size_t)k * Nq + col0 + c];
    }
    __syncthreads();

    const int warp = tid >> 5;
    const int lane = tid & 31;  // = batch b for the K-reduction
    unsigned* my_chunk_cnt = &g_gcnt[warp * 32];    // counter gating THIS warp's k chunk

    // epilogue mapping (first 256 threads): thread -> (eb, ec)
    const bool epi = (tid < Bq * NCOL);
    const int eb = (tid >> 3) & 31;
    const int ec = tid & 7;
    const int en = col0 + ec;
    const float nz = epi ? NOISE_C * noise[eb * Nq + en] : 0.f;
    float* outp = out + (size_t)eb * Tq * Nq + en;
    float* sW0 = &((float*)&g_S4[0][en >> 2][eb])[en & 3];
    float* sW1 = &((float*)&g_S4[1][en >> 2][eb])[en & 3];

    const ulonglong2* Wp0 = (const ulonglong2*)&Wsm[warp * KSL][0];

    for (int t = 1; t < Tq; ++t) {
        const float4* Sp = ((const float4*)g_S4[(t - 1) & 1]) + warp * (ITS * Bq) + lane;

        float xin = epi ? outp[(size_t)t * Nq] : 0.f;  // own data; gate-independent

        // ---- per-warp gate: wait for OUR chunk's producers (prev step) ----
        const unsigned tgt = (unsigned)GSZ * (unsigned)(t - 1);
        if (lane == 0) {
            unsigned v;
            do {
                asm volatile("ld.acquire.gpu.u32 %0, [%1];"
                             : "=r"(v) : "l"(my_chunk_cnt) : "memory");
                if (v < tgt) __nanosleep(8);
            } while (v < tgt);
        }
        __syncwarp();

        // prefetch entire chunk: 16 L2-only float4 loads, MLP=16
        float4 buf[ITS];
#pragma unroll
        for (int j = 0; j < ITS; ++j) buf[j] = __ldcg(Sp + j * Bq);

        unsigned long long a0 = 0, a1 = 0, a2 = 0, a3 = 0;
        const ulonglong2* wp = Wp0;

#pragma unroll
        for (int it = 0; it < ITS; ++it) {
            float4 s = buf[it];
#pragma unroll
            for (int kk = 0; kk < 4; ++kk) {
                unsigned sb = __float_as_uint(kk == 0 ? s.x : kk == 1 ? s.y
                                                         : kk == 2 ? s.z : s.w);
                unsigned long long svv;
                asm("mov.b64 %0, {%1, %1};" : "=l"(svv) : "r"(sb));
                ulonglong2 u0 = wp[0];
                ulonglong2 u1 = wp[1];
                wp += 2;
                asm("fma.rn.f32x2 %0, %1, %2, %0;" : "+l"(a0) : "l"(svv), "l"(u0.x));
                asm("fma.rn.f32x2 %0, %1, %2, %0;" : "+l"(a1) : "l"(svv), "l"(u0.y));
                asm("fma.rn.f32x2 %0, %1, %2, %0;" : "+l"(a2) : "l"(svv), "l"(u1.x));
                asm("fma.rn.f32x2 %0, %1, %2, %0;" : "+l"(a3) : "l"(svv), "l"(u1.y));
            }
        }

        red[warp][lane][0] = __uint_as_float((unsigned)a0);
        red[warp][lane][1] = __uint_as_float((unsigned)(a0 >> 32));
        red[warp][lane][2] = __uint_as_float((unsigned)a1);
        red[warp][lane][3] = __uint_as_float((unsigned)(a1 >> 32));
        red[warp][lane][4] = __uint_as_float((unsigned)a2);
        red[warp][lane][5] = __uint_as_float((unsigned)(a2 >> 32));
        red[warp][lane][6] = __uint_as_float((unsigned)a3);
        red[warp][lane][7] = __uint_as_float((unsigned)(a3 >> 32));
        __syncthreads();

        if (epi) {
            float sum = 0.f;
#pragma unroll
            for (int w = 0; w < NW; ++w) sum += red[w][eb][ec];

            float post = tanhf(sum + xin) + nz;
            outp[(size_t)t * Nq] = post;        // only our own sector — safe
            *((t & 1) ? sW1 : sW0) = post;      // next-step state (read via __ldcg)
        }

        // ---- arrive at own group counter (release publishes state writes) ----
        __syncthreads();  // all CTA state writes done; HB to thread 0
        if (tid == 0) {
            asm volatile("red.release.gpu.add.u32 [%0], %1;"
                         :: "l"(own_cnt), "r"(1u) : "memory");
        }
    }
}

extern "C" void kernel_launch(void* const* d_in, const int* in_sizes, int n_in,
                              void* d_out, int out_size) {
    (void)in_sizes; (void)n_in; (void)out_size;
    const float* x       = (const float*)d_in[0];
    const float* w_input = (const float*)d_in[1];
    const float* w_res   = (const float*)d_in[2];
    const float* w_scale = (const float*)d_in[3];
    const float* states0 = (const float*)d_in[4];
    const float* step0   = (const float*)d_in[5];
    const float* rnoise  = (const float*)d_in[6];
    float* out = (float*)d_out;

    // order: xin, init, recur (recur = late launch -> ncu -s 5 lands on a real kernel)
    dim3 g(8, 128);
    xin_gemm<<<g, 512>>>(x, w_input, w_scale, out);
    init_kernel<<<128, 256>>>(states0, step0, out);
    recur_kernel<<<GRID_G, NTHR>>>(w_res, rnoise, out);
}